// round 1
// baseline (speedup 1.0000x reference)
#include <cuda_runtime.h>
#include <math.h>

#define BATCH 8
#define SEQ   2048
#define DIM   128
#define HDIM  128
#define MASK_VALUE -1e30f

// Scratch for projected q and k (8 MB each) — device globals, no allocation.
__device__ float g_q[BATCH * SEQ * HDIM];
__device__ float g_k[BATCH * SEQ * HDIM];

// ---------------------------------------------------------------------------
// Projection GEMM: Out[m, h] = sum_d X[m, d] * W[d, h]
// M = BATCH*SEQ = 16384, N = 128, K = 128.
// Block tile 128(M) x 128(N), 256 threads, 8x8 micro-tile per thread.
// blockIdx.y selects (query,Wq)->g_q vs (key,Wk)->g_k.
// ---------------------------------------------------------------------------
__global__ __launch_bounds__(256) void proj_kernel(const float* __restrict__ Xq,
                                                   const float* __restrict__ Xk,
                                                   const float* __restrict__ Wq,
                                                   const float* __restrict__ Wk) {
    __shared__ float As[8][128];   // [k][m]
    __shared__ float Bs[8][128];   // [k][n]

    const int tid = threadIdx.x;
    const int tx  = tid & 15;      // column group
    const int ty  = tid >> 4;      // row group
    const int m0  = blockIdx.x * 128;

    const float* __restrict__ X = (blockIdx.y == 0) ? Xq : Xk;
    const float* __restrict__ W = (blockIdx.y == 0) ? Wq : Wk;
    float* __restrict__ Out     = (blockIdx.y == 0) ? g_q : g_k;

    float acc[8][8];
#pragma unroll
    for (int i = 0; i < 8; i++)
#pragma unroll
        for (int j = 0; j < 8; j++) acc[i][j] = 0.f;

    for (int k0 = 0; k0 < DIM; k0 += 8) {
        // Load A tile (128 rows x 8 k), stored transposed As[k][m].
        {
            const int row = tid >> 1;
            const int u   = (tid & 1) * 4;
            float4 x = *(const float4*)&X[(size_t)(m0 + row) * DIM + k0 + u];
            As[u + 0][row] = x.x;
            As[u + 1][row] = x.y;
            As[u + 2][row] = x.z;
            As[u + 3][row] = x.w;
        }
        // Load B tile (8 k x 128 n).
        {
            const int kk = tid >> 5;
            const int n0 = (tid & 31) * 4;
            *(float4*)&Bs[kk][n0] = *(const float4*)&W[(size_t)(k0 + kk) * HDIM + n0];
        }
        __syncthreads();

#pragma unroll
        for (int k = 0; k < 8; k++) {
            float ra[8], rb[8];
            *(float4*)&ra[0] = *(float4*)&As[k][ty * 8];
            *(float4*)&ra[4] = *(float4*)&As[k][ty * 8 + 4];
#pragma unroll
            for (int nn = 0; nn < 8; nn++) rb[nn] = Bs[k][tx + 16 * nn];
#pragma unroll
            for (int rr = 0; rr < 8; rr++)
#pragma unroll
                for (int nn = 0; nn < 8; nn++)
                    acc[rr][nn] = fmaf(ra[rr], rb[nn], acc[rr][nn]);
        }
        __syncthreads();
    }

#pragma unroll
    for (int rr = 0; rr < 8; rr++)
#pragma unroll
        for (int nn = 0; nn < 8; nn++)
            Out[(size_t)(m0 + ty * 8 + rr) * HDIM + tx + 16 * nn] = acc[rr][nn];
}

// ---------------------------------------------------------------------------
// Fused masked-softmax attention (flash style), fp32.
// Block: 64 queries x full head (128). 256 threads = 16x16.
// Thread owns S rows ty*4..+4, S cols {tx + 16*jj}, O cols {tx + 16*dd}.
// Smem tiles padded/transposed so every inner-loop LDS is <=2-way conflicted.
// ---------------------------------------------------------------------------
#define BM 64
#define BN 64
#define QSTR 132   // Qs row stride (floats)
#define KSTR 132   // Ks row stride
#define VSTR 68    // VsT row stride (transposed: [d][j])
#define PSTR 68    // Ps row stride

// floats: Qs 64*132 + Ks 64*132 + VsT 128*68 + Ps 64*68 + ms 64
#define ATTN_SMEM_FLOATS (64 * QSTR + 64 * KSTR + 128 * VSTR + 64 * PSTR + 64)
#define ATTN_SMEM_BYTES  (ATTN_SMEM_FLOATS * 4)

extern __shared__ float smem_attn[];

__global__ __launch_bounds__(256) void attn_kernel(const float* __restrict__ Vg,
                                                   const float* __restrict__ maskg,
                                                   float* __restrict__ Outg) {
    float* Qs  = smem_attn;
    float* Ks  = Qs + 64 * QSTR;
    float* VsT = Ks + 64 * KSTR;
    float* Ps  = VsT + 128 * VSTR;
    float* ms  = Ps + 64 * PSTR;

    const int tid = threadIdx.x;
    const int tx  = tid & 15;
    const int ty  = tid >> 4;
    const int b   = blockIdx.y;
    const int q0  = blockIdx.x * BM;

    const float* __restrict__ qg     = g_q + ((size_t)b * SEQ + q0) * HDIM;
    const float* __restrict__ kgbase = g_k + (size_t)b * SEQ * HDIM;
    const float* __restrict__ vgbase = Vg + (size_t)b * SEQ * DIM;
    const float* __restrict__ mbase  = maskg + (size_t)b * SEQ;

    // Load Q tile (64 x 128).
#pragma unroll
    for (int i = tid; i < 64 * 32; i += 256) {
        const int row = i >> 5;
        const int c4  = (i & 31) * 4;
        *(float4*)&Qs[row * QSTR + c4] = *(const float4*)&qg[(size_t)row * HDIM + c4];
    }

    float m_cur[4], l_cur[4], acc[4][8];
#pragma unroll
    for (int ii = 0; ii < 4; ii++) {
        m_cur[ii] = -INFINITY;
        l_cur[ii] = 0.f;
#pragma unroll
        for (int dd = 0; dd < 8; dd++) acc[ii][dd] = 0.f;
    }

    for (int k0 = 0; k0 < SEQ; k0 += BN) {
        __syncthreads();  // previous PV must be done before overwriting Ks/VsT

        // Load K tile (row-major, padded).
#pragma unroll
        for (int i = tid; i < 64 * 32; i += 256) {
            const int row = i >> 5;
            const int c4  = (i & 31) * 4;
            *(float4*)&Ks[row * KSTR + c4] =
                *(const float4*)&kgbase[(size_t)(k0 + row) * HDIM + c4];
        }
        // Load V tile transposed: VsT[d][j].
#pragma unroll
        for (int i = tid; i < 64 * 32; i += 256) {
            const int row = i >> 5;
            const int c4  = (i & 31) * 4;
            float4 v = *(const float4*)&vgbase[(size_t)(k0 + row) * DIM + c4];
            VsT[(c4 + 0) * VSTR + row] = v.x;
            VsT[(c4 + 1) * VSTR + row] = v.y;
            VsT[(c4 + 2) * VSTR + row] = v.z;
            VsT[(c4 + 3) * VSTR + row] = v.w;
        }
        if (tid < BN) ms[tid] = mbase[k0 + tid];
        __syncthreads();

        // ---- S = Q @ K^T (64x64), thread computes 4x4 at cols tx+16*jj ----
        float s[4][4];
#pragma unroll
        for (int ii = 0; ii < 4; ii++)
#pragma unroll
            for (int jj = 0; jj < 4; jj++) s[ii][jj] = 0.f;

#pragma unroll 4
        for (int d0 = 0; d0 < HDIM; d0 += 4) {
            float4 rq[4], rk[4];
#pragma unroll
            for (int ii = 0; ii < 4; ii++)
                rq[ii] = *(float4*)&Qs[(ty * 4 + ii) * QSTR + d0];
#pragma unroll
            for (int jj = 0; jj < 4; jj++)
                rk[jj] = *(float4*)&Ks[(tx + 16 * jj) * KSTR + d0];
#pragma unroll
            for (int ii = 0; ii < 4; ii++)
#pragma unroll
                for (int jj = 0; jj < 4; jj++) {
                    s[ii][jj] = fmaf(rq[ii].x, rk[jj].x, s[ii][jj]);
                    s[ii][jj] = fmaf(rq[ii].y, rk[jj].y, s[ii][jj]);
                    s[ii][jj] = fmaf(rq[ii].z, rk[jj].z, s[ii][jj]);
                    s[ii][jj] = fmaf(rq[ii].w, rk[jj].w, s[ii][jj]);
                }
        }

        // ---- mask + online softmax ----
        float mv[4];
#pragma unroll
        for (int jj = 0; jj < 4; jj++) mv[jj] = ms[tx + 16 * jj];
#pragma unroll
        for (int ii = 0; ii < 4; ii++)
#pragma unroll
            for (int jj = 0; jj < 4; jj++)
                s[ii][jj] = mv[jj] * s[ii][jj] + (1.f - mv[jj]) * MASK_VALUE;

#pragma unroll
        for (int ii = 0; ii < 4; ii++) {
            float mx = s[ii][0];
#pragma unroll
            for (int jj = 1; jj < 4; jj++) mx = fmaxf(mx, s[ii][jj]);
#pragma unroll
            for (int off = 8; off >= 1; off >>= 1)
                mx = fmaxf(mx, __shfl_xor_sync(0xffffffffu, mx, off, 16));

            const float mnew  = fmaxf(m_cur[ii], mx);
            const float alpha = __expf(m_cur[ii] - mnew);  // exp(-inf)=0 first tile
            float rs = 0.f;
#pragma unroll
            for (int jj = 0; jj < 4; jj++) {
                const float p = __expf(s[ii][jj] - mnew);
                s[ii][jj] = p;
                rs += p;
            }
#pragma unroll
            for (int off = 8; off >= 1; off >>= 1)
                rs += __shfl_xor_sync(0xffffffffu, rs, off, 16);

            l_cur[ii] = l_cur[ii] * alpha + rs;
            m_cur[ii] = mnew;
#pragma unroll
            for (int dd = 0; dd < 8; dd++) acc[ii][dd] *= alpha;
#pragma unroll
            for (int jj = 0; jj < 4; jj++)
                Ps[(ty * 4 + ii) * PSTR + tx + 16 * jj] = s[ii][jj];
        }
        __syncthreads();

        // ---- O += P @ V (P from smem, V transposed) ----
#pragma unroll 2
        for (int j0 = 0; j0 < BN; j0 += 4) {
            float4 rp[4], rv[8];
#pragma unroll
            for (int ii = 0; ii < 4; ii++)
                rp[ii] = *(float4*)&Ps[(ty * 4 + ii) * PSTR + j0];
#pragma unroll
            for (int dd = 0; dd < 8; dd++)
                rv[dd] = *(float4*)&VsT[(tx + 16 * dd) * VSTR + j0];
#pragma unroll
            for (int ii = 0; ii < 4; ii++)
#pragma unroll
                for (int dd = 0; dd < 8; dd++) {
                    acc[ii][dd] = fmaf(rp[ii].x, rv[dd].x, acc[ii][dd]);
                    acc[ii][dd] = fmaf(rp[ii].y, rv[dd].y, acc[ii][dd]);
                    acc[ii][dd] = fmaf(rp[ii].z, rv[dd].z, acc[ii][dd]);
                    acc[ii][dd] = fmaf(rp[ii].w, rv[dd].w, acc[ii][dd]);
                }
        }
    }

    // ---- epilogue: normalize and write out ----
#pragma unroll
    for (int ii = 0; ii < 4; ii++) {
        const float inv = (l_cur[ii] > 0.f) ? (1.f / l_cur[ii]) : 0.f;
        const size_t row = (size_t)b * SEQ + q0 + ty * 4 + ii;
#pragma unroll
        for (int dd = 0; dd < 8; dd++)
            Outg[row * DIM + tx + 16 * dd] = acc[ii][dd] * inv;
    }
}

// ---------------------------------------------------------------------------
extern "C" void kernel_launch(void* const* d_in, const int* in_sizes, int n_in,
                              void* d_out, int out_size) {
    (void)in_sizes; (void)n_in; (void)out_size;
    const float* query = (const float*)d_in[0];
    const float* key   = (const float*)d_in[1];
    const float* value = (const float*)d_in[2];
    const float* mask  = (const float*)d_in[3];
    const float* Wq    = (const float*)d_in[4];
    const float* Wk    = (const float*)d_in[5];
    float* out = (float*)d_out;

    cudaFuncSetAttribute(attn_kernel, cudaFuncAttributeMaxDynamicSharedMemorySize,
                         ATTN_SMEM_BYTES);

    // Projections: q = query@Wq, k = key@Wk into device scratch.
    proj_kernel<<<dim3(BATCH * SEQ / 128, 2), 256>>>(query, key, Wq, Wk);

    // Fused masked softmax attention.
    attn_kernel<<<dim3(SEQ / BM, BATCH), 256, ATTN_SMEM_BYTES>>>(value, mask, out);
}